// round 15
// baseline (speedup 1.0000x reference)
#include <cuda_runtime.h>
#include <cstdint>

#define B       8
#define NA      100800
#define NC      85
#define NCLS    80
#define K_PRE   1024
#define MAX_DET 100
#define NBINS   8192
#define CAP     2048
#define CONF    0.25f
#define IOU_T   0.45f
#define MAXWH   7680.0f

#define S_ANCH   256                        // anchors per tile (== threads per score block)
#define NT       ((B * NA) / S_ANCH)        // 3150 tiles
#define TILE_B   (S_ANCH * NC * 4)          // 87040 bytes per tile
#define SGRID    148                        // 1 block/SM

#define BPB      16                         // tail blocks per batch
#define TGRID    (B * BPB)                  // 128 blocks, all co-resident
#define VB       (NA / 4)                   // 25200 uint4 per batch
#define VPB      (VB / BPB)                 // 1575 uint4 per gather block

// ---------------- device scratch (no allocations allowed) ----------------
__device__ uint32_t           g_keys[B * NA];
__device__ uint8_t            g_cls [B * NA];
__device__ uint32_t           g_hist[B * NBINS];   // zero-init; re-zeroed in phase C
__device__ int                g_cnt [B];           // zero-init; re-zeroed in phase D
__device__ unsigned long long g_cand[B * CAP];
__device__ float4             g_bx  [B * K_PRE];
__device__ float              g_area[B * K_PRE];
__device__ float4             g_raw [B * K_PRE];
__device__ float2             g_sc  [B * K_PRE];
// per-batch barrier, one 128B line per batch: [0]=count, [1]=generation
__device__ unsigned int       g_bar2[B][32];

// ---------------- mbarrier / TMA-bulk helpers ----------------
__device__ __forceinline__ uint32_t smem_u32(const void* p) {
    return (uint32_t)__cvta_generic_to_shared(p);
}
__device__ __forceinline__ void mbar_init(uint32_t mbar, uint32_t count) {
    asm volatile("mbarrier.init.shared.b64 [%0], %1;" :: "r"(mbar), "r"(count) : "memory");
}
__device__ __forceinline__ void mbar_expect_tx(uint32_t mbar, uint32_t bytes) {
    asm volatile("mbarrier.arrive.expect_tx.shared.b64 _, [%0], %1;"
                 :: "r"(mbar), "r"(bytes) : "memory");
}
__device__ __forceinline__ void bulk_g2s(uint32_t dst, const void* src,
                                         uint32_t bytes, uint32_t mbar) {
    asm volatile("cp.async.bulk.shared::cta.global.mbarrier::complete_tx::bytes "
                 "[%0], [%1], %2, [%3];"
                 :: "r"(dst), "l"(src), "r"(bytes), "r"(mbar) : "memory");
}
__device__ __forceinline__ void mbar_wait(uint32_t mbar, uint32_t phase) {
    uint32_t done;
    asm volatile(
        "{\n\t.reg .pred p;\n\t"
        "mbarrier.try_wait.parity.acquire.cta.shared::cta.b64 p, [%1], %2;\n\t"
        "selp.b32 %0, 1, 0, p;\n\t}"
        : "=r"(done) : "r"(mbar), "r"(phase) : "memory");
    if (!done) {
        asm volatile(
            "{\n\t.reg .pred P1;\n\t"
            "WL_%=:\n\t"
            "mbarrier.try_wait.parity.acquire.cta.shared::cta.b64 P1, [%0], %1, 0x989680;\n\t"
            "@P1 bra.uni WD_%=;\n\t"
            "bra.uni WL_%=;\n\t"
            "WD_%=:\n\t}"
            :: "r"(mbar), "r"(phase) : "memory");
    }
}

// ---------------- per-batch software barrier (16 blocks) ----------------
__device__ __forceinline__ void batch_bar(int b) {
    __syncthreads();
    if (threadIdx.x == 0) {
        __threadfence();
        unsigned int gen = *((volatile unsigned int*)&g_bar2[b][1]);
        unsigned int old = atomicAdd(&g_bar2[b][0], 1u);
        if (old == BPB - 1) {
            *((volatile unsigned int*)&g_bar2[b][0]) = 0u;
            __threadfence();
            atomicAdd(&g_bar2[b][1], 1u);
        } else {
            while (*((volatile unsigned int*)&g_bar2[b][1]) == gen) { }
        }
        __threadfence();
    }
    __syncthreads();
}

// ---------------- kernel 1: score/cls — TMA-bulk double-buffered streaming ----------------
__global__ void __launch_bounds__(S_ANCH)
score_kernel(const float* __restrict__ pred) {
    extern __shared__ float sb[];               // 2 tiles: 174080 B
    __shared__ alignas(8) unsigned long long barst[2];
    int t = threadIdx.x;
    uint32_t sb_u32  = smem_u32(sb);
    uint32_t bar_u32 = smem_u32(barst);

    if (t == 0) { mbar_init(bar_u32, 1); mbar_init(bar_u32 + 8, 1); }
    __syncthreads();

    int tile0 = blockIdx.x;
    if (tile0 < NT && t == 0) {
        mbar_expect_tx(bar_u32, TILE_B);
        bulk_g2s(sb_u32, pred + (size_t)tile0 * (S_ANCH * NC), TILE_B, bar_u32);
    }

    int ph0 = 0, ph1 = 0;
    int parity = 0;
    for (int tile = tile0; tile < NT; tile += SGRID) {
        int next = tile + SGRID;
        if (next < NT && t == 0) {
            uint32_t b2 = bar_u32 + (parity ^ 1) * 8;
            mbar_expect_tx(b2, TILE_B);
            bulk_g2s(sb_u32 + (parity ^ 1) * TILE_B,
                     pred + (size_t)next * (S_ANCH * NC), TILE_B, b2);
        }
        if (parity == 0) { mbar_wait(bar_u32,     ph0); ph0 ^= 1; }
        else             { mbar_wait(bar_u32 + 8, ph1); ph1 ^= 1; }

        const float* p = sb + parity * (S_ANCH * NC) + t * NC;  // stride 85: conflict-free
        float obj = p[4];

        uint32_t key = 0u;
        uint32_t cls = 0u;
        if (obj > CONF) {
            float m0 = -1.f, m1 = -1.f, m2 = -1.f, m3 = -1.f;
            int   i0 = 0,    i1 = 0,    i2 = 0,    i3 = 0;
            #pragma unroll
            for (int k = 0; k < 20; k++) {
                float c0 = __fmul_rn(p[5 + k],      obj);
                float c1 = __fmul_rn(p[5 + 20 + k], obj);
                float c2 = __fmul_rn(p[5 + 40 + k], obj);
                float c3 = __fmul_rn(p[5 + 60 + k], obj);
                if (c0 > m0) { m0 = c0; i0 = k; }
                if (c1 > m1) { m1 = c1; i1 = 20 + k; }
                if (c2 > m2) { m2 = c2; i2 = 40 + k; }
                if (c3 > m3) { m3 = c3; i3 = 60 + k; }
            }
            float best = m0; int bid = i0;
            if (m1 > best) { best = m1; bid = i1; }
            if (m2 > best) { best = m2; bid = i2; }
            if (m3 > best) { best = m3; bid = i3; }

            if (best > CONF) {
                key = __float_as_uint(best);
                cls = (uint32_t)bid;
                int anchor = tile * S_ANCH + t;
                int b = anchor / NA;
                int bin = (int)(best * (float)NBINS);
                if (bin > NBINS - 1) bin = NBINS - 1;
                atomicAdd(&g_hist[b * NBINS + bin], 1u);
            }
        }
        int anchor = tile * S_ANCH + t;
        g_keys[anchor] = key;
        g_cls [anchor] = (uint8_t)cls;

        __syncthreads();
        parity ^= 1;
    }
}

// ---------------- kernel 2: fused tail, per-batch pipelined ----------------
__global__ void __launch_bounds__(1024)
tail_kernel(const float* __restrict__ pred, float* __restrict__ out) {
    __shared__ alignas(16) unsigned char ubuf[1024 * 20 + 512];
    __shared__ int  s_ws[33];
    __shared__ uint32_t keep_s[32];
    __shared__ int  pfx[33];
    __shared__ uint32_t classbits[NCLS][32];     // 10240 B
    __shared__ int      cbase[NCLS + 1];
    __shared__ uint16_t clist[K_PRE];
    __shared__ uint8_t  keep8[K_PRE];

    int tid = threadIdx.x;
    int blk = blockIdx.x;
    int lane = tid & 31, wid = tid >> 5;
    const unsigned F = 0xffffffffu;

    int b_my = blk >> 4;      // this block's batch
    int sub  = blk & 15;

    // ===== phase A: every block computes its own batch's threshold T =====
    int T;
    {
        if (tid == 0) s_ws[32] = 0;
        int base = NBINS - 1 - 8 * tid;          // 8 descending bins per thread
        int cnts[8]; int ssum = 0;
        #pragma unroll
        for (int k = 0; k < 8; k++) {
            cnts[k] = (int)g_hist[b_my * NBINS + base - k];
            ssum += cnts[k];
        }
        int ps = ssum;
        #pragma unroll
        for (int o = 1; o < 32; o <<= 1) { int v = __shfl_up_sync(F, ps, o); if (lane >= o) ps += v; }
        if (lane == 31) s_ws[wid] = ps;
        __syncthreads();
        if (wid == 0) {
            int p2 = s_ws[lane];
            #pragma unroll
            for (int o = 1; o < 32; o <<= 1) { int u = __shfl_up_sync(F, p2, o); if (lane >= o) p2 += u; }
            s_ws[lane] = p2;
        }
        __syncthreads();
        int cum  = ps + (wid > 0 ? s_ws[wid - 1] : 0);
        int prev = cum - ssum;
        if (prev < K_PRE && cum >= K_PRE) {
            int acc = prev, TT = 0;
            #pragma unroll
            for (int k = 0; k < 8; k++) { acc += cnts[k]; if (acc >= K_PRE) { TT = base - k; break; } }
            s_ws[32] = TT;
        }
        __syncthreads();
        T = s_ws[32];
        __syncthreads();                          // s_ws reused below
    }

    // ===== phase B: gather (16 blocks/batch) + per-batch slot pre-zero =====
    {
        int* s_cnt  = &s_ws[0];
        int* s_base = &s_ws[1];
        if (tid == 0) *s_cnt = 0;
        __syncthreads();

        uint32_t ks[8]; int pos[8]; bool pass[8];
        #pragma unroll
        for (int u = 0; u < 8; u++) { ks[u] = 0u; pass[u] = false; }

        #pragma unroll
        for (int it = 0; it < 2; it++) {
            int v = sub * VPB + it * 1024 + tid;
            if (v < (sub + 1) * VPB) {
                uint4 k4 = *(const uint4*)(g_keys + (size_t)b_my * NA + v * 4);
                uint32_t kk[4] = {k4.x, k4.y, k4.z, k4.w};
                #pragma unroll
                for (int u = 0; u < 4; u++) {
                    uint32_t key = kk[u];
                    if (!key) continue;
                    float s = __uint_as_float(key);
                    int bin = (int)(s * (float)NBINS);
                    if (bin > NBINS - 1) bin = NBINS - 1;
                    if (bin < T) continue;
                    ks[it * 4 + u]  = key;
                    pos[it * 4 + u] = atomicAdd(s_cnt, 1);
                    pass[it * 4 + u] = true;
                }
            }
        }
        __syncthreads();
        if (tid == 0) *s_base = (*s_cnt > 0) ? atomicAdd(&g_cnt[b_my], *s_cnt) : 0;
        __syncthreads();
        int sbase = *s_base;
        #pragma unroll
        for (int it = 0; it < 2; it++) {
            int v = sub * VPB + it * 1024 + tid;
            #pragma unroll
            for (int u = 0; u < 4; u++) {
                if (pass[it * 4 + u]) {
                    int p = sbase + pos[it * 4 + u];
                    if (p < CAP) {
                        uint32_t li = (uint32_t)(v * 4 + u);
                        g_cand[b_my * CAP + p] =
                            ((unsigned long long)ks[it * 4 + u] << 32) |
                            (unsigned long long)(0xFFFFFFFFu - li);
                    }
                }
            }
        }
        // per-batch slot pre-zero: 16 blocks x 64 slots = 1024
        if (tid < 64) {
            int s = b_my * K_PRE + sub * 64 + tid;
            g_sc  [s] = make_float2(0.f, 0.f);
            g_bx  [s] = make_float4(0.f, 0.f, 0.f, 0.f);
            g_area[s] = 0.f;
        }
    }
    batch_bar(b_my);

    // ===== phase C: rank + per-batch hist re-zero =====
    {
        // hist re-zero: 16 blocks x 512 words = 8192
        if (tid < 512) g_hist[b_my * NBINS + sub * 512 + tid] = 0u;

        unsigned long long* sk = (unsigned long long*)ubuf;
        int cnt = g_cnt[b_my];
        if (cnt > CAP) cnt = CAP;
        int cntP = (cnt + 127) & ~127;

        if (sub * 128 < cnt) {
            for (int j = tid; j < cntP; j += 1024)
                sk[j] = (j < cnt) ? g_cand[b_my * CAP + j] : 0ull;
            __syncthreads();

            int ibase = sub * 128 + wid;
            unsigned long long k0 = 0, k1 = 0, k2 = 0, k3 = 0;
            bool v0 = ibase      < cnt, v1 = ibase+32 < cnt,
                 v2 = ibase+64 < cnt,   v3 = ibase+96 < cnt;
            if (v0) k0 = sk[ibase];
            if (v1) k1 = sk[ibase + 32];
            if (v2) k2 = sk[ibase + 64];
            if (v3) k3 = sk[ibase + 96];

            int c0 = 0, c1 = 0, c2 = 0, c3 = 0;
            for (int j = lane; j < cntP; j += 32) {
                unsigned long long v = sk[j];
                c0 += (v > k0); c1 += (v > k1); c2 += (v > k2); c3 += (v > k3);
            }
            int r0 = __reduce_add_sync(F, c0);
            int r1 = __reduce_add_sync(F, c1);
            int r2 = __reduce_add_sync(F, c2);
            int r3 = __reduce_add_sync(F, c3);

            unsigned long long kil[4] = {k0, k1, k2, k3};
            int  rl[4] = {r0, r1, r2, r3};
            bool vl[4] = {v0, v1, v2, v3};
            if (lane < 4 && vl[lane] && rl[lane] < K_PRE) {
                unsigned long long ki = kil[lane];
                int rank = rl[lane];
                float score = __uint_as_float((uint32_t)(ki >> 32));
                uint32_t idx = 0xFFFFFFFFu - (uint32_t)ki;

                const float* pr = pred + ((size_t)b_my * NA + idx) * NC;
                float cx = pr[0], cy = pr[1], w = pr[2], h = pr[3];
                float x1 = __fsub_rn(cx, __fmul_rn(w, 0.5f));
                float y1 = __fsub_rn(cy, __fmul_rn(h, 0.5f));
                float x2 = __fadd_rn(cx, __fmul_rn(w, 0.5f));
                float y2 = __fadd_rn(cy, __fmul_rn(h, 0.5f));
                float clsf = (float)g_cls[b_my * NA + idx];
                float off  = __fmul_rn(clsf, MAXWH);
                float ox1 = __fadd_rn(x1, off), oy1 = __fadd_rn(y1, off);
                float ox2 = __fadd_rn(x2, off), oy2 = __fadd_rn(y2, off);

                int s = b_my * K_PRE + rank;
                g_bx  [s] = make_float4(ox1, oy1, ox2, oy2);
                g_area[s] = __fmul_rn(__fsub_rn(ox2, ox1), __fsub_rn(oy2, oy1));
                g_raw [s] = make_float4(x1, y1, x2, y2);
                g_sc  [s] = make_float2(score, clsf);
            }
        }
    }
    batch_bar(b_my);

    // ===== phase D+E: per-class serial greedy NMS + output (block sub==0 only) =====
    if (sub != 0) return;
    {
        if (tid == 0) g_cnt[b_my] = 0;   // last reader was phase C

        float4* jb4 = (float4*)ubuf;                    // 1024 * 16B
        float*  ja  = (float*)(ubuf + 1024 * 16);       // 1024 * 4B

        jb4[tid] = g_bx  [b_my * K_PRE + tid];
        ja [tid] = g_area[b_my * K_PRE + tid];
        float2 sc = g_sc[b_my * K_PRE + tid];
        bool valid = sc.x > 0.0f;
        int  cls   = (int)sc.y;

        // zero class bitmasks + keep flags
        #pragma unroll
        for (int r = 0; r < (NCLS * 32 + 1023) / 1024; r++) {
            int i = r * 1024 + tid;
            if (i < NCLS * 32) ((uint32_t*)classbits)[i] = 0u;
        }
        keep8[tid] = 0;
        __syncthreads();

        if (valid) atomicOr(&classbits[cls][tid >> 5], 1u << (tid & 31));
        __syncthreads();

        // per-class counts -> bases (rank-ordered segments via prefix popcount)
        if (tid < NCLS) {
            int s = 0;
            #pragma unroll
            for (int w = 0; w < 32; w++) s += __popc(classbits[tid][w]);
            cbase[tid + 1] = s;
        }
        __syncthreads();
        if (tid == 0) {
            cbase[0] = 0;
            for (int c = 0; c < NCLS; c++) cbase[c + 1] += cbase[c];
        }
        __syncthreads();
        if (valid) {
            int pos = 0;
            int myw = tid >> 5;
            for (int w = 0; w < myw; w++) pos += __popc(classbits[cls][w]);
            pos += __popc(classbits[cls][myw] & ((1u << (tid & 31)) - 1u));
            clist[cbase[cls] + pos] = (uint16_t)tid;   // ascending tid == ascending rank
        }
        __syncthreads();

        // warp wid handles classes wid, wid+32, wid+64 — exact serial greedy per class
        for (int c = wid; c < NCLS; c += 32) {
            int s0 = cbase[c];
            int m  = cbase[c + 1] - s0;
            if (m == 0) continue;

            uint32_t sup = 0, kept = 0;   // bit k = entry (lane + 32k); m <= 1024
            for (int q = 0; q < m; q++) {
                uint32_t sup_owner = __shfl_sync(F, sup, q & 31);
                if ((sup_owner >> (q >> 5)) & 1) continue;    // q already suppressed
                if (lane == (q & 31)) kept |= 1u << (q >> 5); // q survives -> kept
                int tq = clist[s0 + q];
                float4 qb = jb4[tq];
                float  qa = ja [tq];
                for (int k = 0; lane + 32 * k < m; k++) {
                    int e = lane + 32 * k;
                    if (e <= q || ((sup >> k) & 1)) continue;
                    int te = clist[s0 + e];
                    float4 eb = jb4[te];
                    float ltx = fmaxf(eb.x, qb.x), lty = fmaxf(eb.y, qb.y);
                    float rbx = fminf(eb.z, qb.z), rby = fminf(eb.w, qb.w);
                    float ww = fmaxf(__fsub_rn(rbx, ltx), 0.0f);
                    float hh = fmaxf(__fsub_rn(rby, lty), 0.0f);
                    float inter = __fmul_rn(ww, hh);
                    float uni   = __fadd_rn(__fsub_rn(__fadd_rn(ja[te], qa), inter), 1e-7f);
                    float iou   = __fdiv_rn(inter, uni);
                    if (iou > IOU_T) sup |= 1u << k;
                }
            }
            for (int k = 0; lane + 32 * k < m; k++)
                if ((kept >> k) & 1) keep8[clist[s0 + lane + 32 * k]] = 1;
        }
        __syncthreads();

        // ---- rank kept candidates (already in global score order) + output ----
        int b = b_my, t = tid;
        if (t < MAX_DET * 6) out[b * MAX_DET * 6 + t] = 0.0f;

        bool kept = keep8[t] != 0;
        {
            unsigned bal = __ballot_sync(F, kept);
            if (lane == 0) keep_s[wid] = bal;
        }
        __syncthreads();

        if (t == 0) {
            pfx[0] = 0;
            for (int w = 0; w < 32; w++) pfx[w + 1] = pfx[w] + __popc(keep_s[w]);
        }
        __syncthreads();

        uint32_t kw = keep_s[wid];
        if (kept) {
            int rank = pfx[wid] + __popc(kw & ((1u << lane) - 1u));
            if (rank < MAX_DET) {
                float4 r = g_raw[b * K_PRE + t];
                float* o = out + ((size_t)b * MAX_DET + rank) * 6;
                o[0] = r.x; o[1] = r.y; o[2] = r.z; o[3] = r.w;
                o[4] = sc.x; o[5] = sc.y;
            }
        }
    }
}

// ---------------- launcher ----------------
extern "C" void kernel_launch(void* const* d_in, const int* in_sizes, int n_in,
                              void* d_out, int out_size) {
    (void)in_sizes; (void)n_in; (void)out_size;
    const float* pred = (const float*)d_in[0];
    float* out = (float*)d_out;

    static int configured = 0;
    if (!configured) {
        cudaFuncSetAttribute(score_kernel,
                             cudaFuncAttributeMaxDynamicSharedMemorySize, 2 * TILE_B);
        configured = 1;
    }

    score_kernel<<<SGRID, S_ANCH, 2 * TILE_B>>>(pred);
    tail_kernel <<<TGRID, 1024>>>(pred, out);
}

// round 16
// speedup vs baseline: 1.2429x; 1.2429x over previous
#include <cuda_runtime.h>
#include <cstdint>

#define B       8
#define NA      100800
#define NC      85
#define NCLS    80
#define K_PRE   1024
#define MAX_DET 100
#define NBINS   8192
#define CAP     2048
#define CONF    0.25f
#define IOU_T   0.45f
#define MAXWH   7680.0f

#define S_ANCH   256                        // anchors per tile (== threads per score block)
#define NT       ((B * NA) / S_ANCH)        // 3150 tiles
#define TILE_B   (S_ANCH * NC * 4)          // 87040 bytes per tile
#define SGRID    148                        // 1 block/SM

#define BPB      16                         // tail blocks per batch
#define TGRID    (B * BPB)                  // 128 blocks, all co-resident
#define VB       (NA / 4)                   // 25200 uint4 per batch
#define VPB      (VB / BPB)                 // 1575 uint4 per gather block

// ---------------- device scratch (no allocations allowed) ----------------
__device__ uint32_t           g_keys[B * NA];
__device__ uint8_t            g_cls [B * NA];
__device__ uint32_t           g_hist[B * NBINS];   // zero-init; re-zeroed in phase C
__device__ int                g_cnt [B];           // zero-init; re-zeroed in phase D
__device__ unsigned long long g_cand[B * CAP];
__device__ float4             g_bx  [B * K_PRE];
__device__ float              g_area[B * K_PRE];
__device__ float4             g_raw [B * K_PRE];
__device__ float2             g_sc  [B * K_PRE];
__device__ uint32_t           g_maskT[B * 32 * K_PRE];
// per-batch barrier, one 128B line per batch: [0]=count, [1]=generation
__device__ unsigned int       g_bar2[B][32];

// ---------------- mbarrier / TMA-bulk helpers ----------------
__device__ __forceinline__ uint32_t smem_u32(const void* p) {
    return (uint32_t)__cvta_generic_to_shared(p);
}
__device__ __forceinline__ void mbar_init(uint32_t mbar, uint32_t count) {
    asm volatile("mbarrier.init.shared.b64 [%0], %1;" :: "r"(mbar), "r"(count) : "memory");
}
__device__ __forceinline__ void mbar_expect_tx(uint32_t mbar, uint32_t bytes) {
    asm volatile("mbarrier.arrive.expect_tx.shared.b64 _, [%0], %1;"
                 :: "r"(mbar), "r"(bytes) : "memory");
}
__device__ __forceinline__ void bulk_g2s(uint32_t dst, const void* src,
                                         uint32_t bytes, uint32_t mbar) {
    asm volatile("cp.async.bulk.shared::cta.global.mbarrier::complete_tx::bytes "
                 "[%0], [%1], %2, [%3];"
                 :: "r"(dst), "l"(src), "r"(bytes), "r"(mbar) : "memory");
}
__device__ __forceinline__ void mbar_wait(uint32_t mbar, uint32_t phase) {
    uint32_t done;
    asm volatile(
        "{\n\t.reg .pred p;\n\t"
        "mbarrier.try_wait.parity.acquire.cta.shared::cta.b64 p, [%1], %2;\n\t"
        "selp.b32 %0, 1, 0, p;\n\t}"
        : "=r"(done) : "r"(mbar), "r"(phase) : "memory");
    if (!done) {
        asm volatile(
            "{\n\t.reg .pred P1;\n\t"
            "WL_%=:\n\t"
            "mbarrier.try_wait.parity.acquire.cta.shared::cta.b64 P1, [%0], %1, 0x989680;\n\t"
            "@P1 bra.uni WD_%=;\n\t"
            "bra.uni WL_%=;\n\t"
            "WD_%=:\n\t}"
            :: "r"(mbar), "r"(phase) : "memory");
    }
}

// ---------------- per-batch software barrier (16 blocks) ----------------
__device__ __forceinline__ void batch_bar(int b) {
    __syncthreads();
    if (threadIdx.x == 0) {
        __threadfence();
        unsigned int gen = *((volatile unsigned int*)&g_bar2[b][1]);
        unsigned int old = atomicAdd(&g_bar2[b][0], 1u);
        if (old == BPB - 1) {
            *((volatile unsigned int*)&g_bar2[b][0]) = 0u;
            __threadfence();
            atomicAdd(&g_bar2[b][1], 1u);
        } else {
            while (*((volatile unsigned int*)&g_bar2[b][1]) == gen) { }
        }
        __threadfence();
    }
    __syncthreads();
}

// ---------------- kernel 1: score/cls — TMA-bulk double-buffered streaming ----------------
__global__ void __launch_bounds__(S_ANCH)
score_kernel(const float* __restrict__ pred) {
    extern __shared__ float sb[];               // 2 tiles: 174080 B
    __shared__ alignas(8) unsigned long long barst[2];
    int t = threadIdx.x;
    uint32_t sb_u32  = smem_u32(sb);
    uint32_t bar_u32 = smem_u32(barst);

    if (t == 0) { mbar_init(bar_u32, 1); mbar_init(bar_u32 + 8, 1); }
    __syncthreads();

    int tile0 = blockIdx.x;
    if (tile0 < NT && t == 0) {
        mbar_expect_tx(bar_u32, TILE_B);
        bulk_g2s(sb_u32, pred + (size_t)tile0 * (S_ANCH * NC), TILE_B, bar_u32);
    }

    int ph0 = 0, ph1 = 0;
    int parity = 0;
    for (int tile = tile0; tile < NT; tile += SGRID) {
        int next = tile + SGRID;
        if (next < NT && t == 0) {
            uint32_t b2 = bar_u32 + (parity ^ 1) * 8;
            mbar_expect_tx(b2, TILE_B);
            bulk_g2s(sb_u32 + (parity ^ 1) * TILE_B,
                     pred + (size_t)next * (S_ANCH * NC), TILE_B, b2);
        }
        if (parity == 0) { mbar_wait(bar_u32,     ph0); ph0 ^= 1; }
        else             { mbar_wait(bar_u32 + 8, ph1); ph1 ^= 1; }

        const float* p = sb + parity * (S_ANCH * NC) + t * NC;  // stride 85: conflict-free
        float obj = p[4];

        uint32_t key = 0u;
        uint32_t cls = 0u;
        if (obj > CONF) {
            float m0 = -1.f, m1 = -1.f, m2 = -1.f, m3 = -1.f;
            int   i0 = 0,    i1 = 0,    i2 = 0,    i3 = 0;
            #pragma unroll
            for (int k = 0; k < 20; k++) {
                float c0 = __fmul_rn(p[5 + k],      obj);
                float c1 = __fmul_rn(p[5 + 20 + k], obj);
                float c2 = __fmul_rn(p[5 + 40 + k], obj);
                float c3 = __fmul_rn(p[5 + 60 + k], obj);
                if (c0 > m0) { m0 = c0; i0 = k; }
                if (c1 > m1) { m1 = c1; i1 = 20 + k; }
                if (c2 > m2) { m2 = c2; i2 = 40 + k; }
                if (c3 > m3) { m3 = c3; i3 = 60 + k; }
            }
            float best = m0; int bid = i0;
            if (m1 > best) { best = m1; bid = i1; }
            if (m2 > best) { best = m2; bid = i2; }
            if (m3 > best) { best = m3; bid = i3; }

            if (best > CONF) {
                key = __float_as_uint(best);
                cls = (uint32_t)bid;
                int anchor = tile * S_ANCH + t;
                int b = anchor / NA;
                int bin = (int)(best * (float)NBINS);
                if (bin > NBINS - 1) bin = NBINS - 1;
                atomicAdd(&g_hist[b * NBINS + bin], 1u);
            }
        }
        int anchor = tile * S_ANCH + t;
        g_keys[anchor] = key;
        g_cls [anchor] = (uint8_t)cls;

        __syncthreads();
        parity ^= 1;
    }
}

// ---------------- kernel 2: fused tail, per-batch pipelined ----------------
__global__ void __launch_bounds__(1024)
tail_kernel(const float* __restrict__ pred, float* __restrict__ out) {
    __shared__ alignas(16) unsigned char ubuf[1024 * 20 + 512];
    __shared__ int  s_ws[33];
    __shared__ uint32_t keep_s[32];
    __shared__ int  pfx[33];
    __shared__ int  ccnt[NCLS];
    __shared__ int  cbase[NCLS + 1];
    __shared__ uint16_t clist[K_PRE];

    int tid = threadIdx.x;
    int blk = blockIdx.x;
    int lane = tid & 31, wid = tid >> 5;
    const unsigned F = 0xffffffffu;

    int b_my = blk >> 4;      // this block's batch
    int sub  = blk & 15;

    // ===== phase A: per-block threshold T (vectorized hist reads) + out pre-zero =====
    int T;
    {
        if (sub == 0 && tid < MAX_DET * 6) out[b_my * MAX_DET * 6 + tid] = 0.0f;

        if (tid == 0) s_ws[32] = 0;
        // thread tid owns descending bins [NBINS-1-8*tid .. NBINS-8-8*tid],
        // i.e. ascending words [NBINS-8-8*tid .. NBINS-1-8*tid] = 2 aligned uint4
        int lo = NBINS - 8 - 8 * tid;
        const uint4* hp = (const uint4*)&g_hist[b_my * NBINS + lo];
        uint4 h0 = hp[0], h1 = hp[1];
        int cnts[8];   // cnts[k] = bin (NBINS-1-8*tid - k)
        cnts[0] = (int)h1.w; cnts[1] = (int)h1.z; cnts[2] = (int)h1.y; cnts[3] = (int)h1.x;
        cnts[4] = (int)h0.w; cnts[5] = (int)h0.z; cnts[6] = (int)h0.y; cnts[7] = (int)h0.x;
        int ssum = 0;
        #pragma unroll
        for (int k = 0; k < 8; k++) ssum += cnts[k];

        int ps = ssum;
        #pragma unroll
        for (int o = 1; o < 32; o <<= 1) { int v = __shfl_up_sync(F, ps, o); if (lane >= o) ps += v; }
        if (lane == 31) s_ws[wid] = ps;
        __syncthreads();
        if (wid == 0) {
            int p2 = s_ws[lane];
            #pragma unroll
            for (int o = 1; o < 32; o <<= 1) { int u = __shfl_up_sync(F, p2, o); if (lane >= o) p2 += u; }
            s_ws[lane] = p2;
        }
        __syncthreads();
        int cum  = ps + (wid > 0 ? s_ws[wid - 1] : 0);
        int prev = cum - ssum;
        if (prev < K_PRE && cum >= K_PRE) {
            int acc = prev, TT = 0;
            int base = NBINS - 1 - 8 * tid;
            #pragma unroll
            for (int k = 0; k < 8; k++) { acc += cnts[k]; if (acc >= K_PRE) { TT = base - k; break; } }
            s_ws[32] = TT;
        }
        __syncthreads();
        T = s_ws[32];
        __syncthreads();                          // s_ws reused below
    }

    // ===== phase B: gather (16 blocks/batch) + per-batch slot pre-zero =====
    {
        int* s_cnt  = &s_ws[0];
        int* s_base = &s_ws[1];
        if (tid == 0) *s_cnt = 0;
        __syncthreads();

        uint32_t ks[8]; int pos[8]; bool pass[8];
        #pragma unroll
        for (int u = 0; u < 8; u++) { ks[u] = 0u; pass[u] = false; }

        #pragma unroll
        for (int it = 0; it < 2; it++) {
            int v = sub * VPB + it * 1024 + tid;
            if (v < (sub + 1) * VPB) {
                uint4 k4 = *(const uint4*)(g_keys + (size_t)b_my * NA + v * 4);
                uint32_t kk[4] = {k4.x, k4.y, k4.z, k4.w};
                #pragma unroll
                for (int u = 0; u < 4; u++) {
                    uint32_t key = kk[u];
                    if (!key) continue;
                    float s = __uint_as_float(key);
                    int bin = (int)(s * (float)NBINS);
                    if (bin > NBINS - 1) bin = NBINS - 1;
                    if (bin < T) continue;
                    ks[it * 4 + u]  = key;
                    pos[it * 4 + u] = atomicAdd(s_cnt, 1);
                    pass[it * 4 + u] = true;
                }
            }
        }
        __syncthreads();
        if (tid == 0) *s_base = (*s_cnt > 0) ? atomicAdd(&g_cnt[b_my], *s_cnt) : 0;
        __syncthreads();
        int sbase = *s_base;
        #pragma unroll
        for (int it = 0; it < 2; it++) {
            int v = sub * VPB + it * 1024 + tid;
            #pragma unroll
            for (int u = 0; u < 4; u++) {
                if (pass[it * 4 + u]) {
                    int p = sbase + pos[it * 4 + u];
                    if (p < CAP) {
                        uint32_t li = (uint32_t)(v * 4 + u);
                        g_cand[b_my * CAP + p] =
                            ((unsigned long long)ks[it * 4 + u] << 32) |
                            (unsigned long long)(0xFFFFFFFFu - li);
                    }
                }
            }
        }
        // per-batch slot pre-zero: 16 blocks x 64 slots = 1024
        if (tid < 64) {
            int s = b_my * K_PRE + sub * 64 + tid;
            g_sc  [s] = make_float2(0.f, 0.f);
            g_bx  [s] = make_float4(0.f, 0.f, 0.f, 0.f);
            g_area[s] = 0.f;
        }
    }
    batch_bar(b_my);

    // ===== phase C: rank + per-batch hist re-zero + maskT zero =====
    {
        // hist re-zero: 16 blocks x 512 words = 8192
        if (tid < 512) g_hist[b_my * NBINS + sub * 512 + tid] = 0u;
        // maskT zero: 16 blocks x 2048 words = 32768 (batch segment)
        {
            uint2* mz = (uint2*)&g_maskT[(size_t)b_my * 32 * K_PRE];
            mz[sub * 1024 + tid] = make_uint2(0u, 0u);
        }

        unsigned long long* sk = (unsigned long long*)ubuf;
        int cnt = g_cnt[b_my];
        if (cnt > CAP) cnt = CAP;
        int cntP = (cnt + 127) & ~127;

        if (sub * 128 < cnt) {
            for (int j = tid; j < cntP; j += 1024)
                sk[j] = (j < cnt) ? g_cand[b_my * CAP + j] : 0ull;
            __syncthreads();

            int ibase = sub * 128 + wid;
            unsigned long long k0 = 0, k1 = 0, k2 = 0, k3 = 0;
            bool v0 = ibase      < cnt, v1 = ibase+32 < cnt,
                 v2 = ibase+64 < cnt,   v3 = ibase+96 < cnt;
            if (v0) k0 = sk[ibase];
            if (v1) k1 = sk[ibase + 32];
            if (v2) k2 = sk[ibase + 64];
            if (v3) k3 = sk[ibase + 96];

            int c0 = 0, c1 = 0, c2 = 0, c3 = 0;
            for (int j = lane; j < cntP; j += 32) {
                unsigned long long v = sk[j];
                c0 += (v > k0); c1 += (v > k1); c2 += (v > k2); c3 += (v > k3);
            }
            int r0 = __reduce_add_sync(F, c0);
            int r1 = __reduce_add_sync(F, c1);
            int r2 = __reduce_add_sync(F, c2);
            int r3 = __reduce_add_sync(F, c3);

            unsigned long long kil[4] = {k0, k1, k2, k3};
            int  rl[4] = {r0, r1, r2, r3};
            bool vl[4] = {v0, v1, v2, v3};
            if (lane < 4 && vl[lane] && rl[lane] < K_PRE) {
                unsigned long long ki = kil[lane];
                int rank = rl[lane];
                float score = __uint_as_float((uint32_t)(ki >> 32));
                uint32_t idx = 0xFFFFFFFFu - (uint32_t)ki;

                const float* pr = pred + ((size_t)b_my * NA + idx) * NC;
                float cx = pr[0], cy = pr[1], w = pr[2], h = pr[3];
                float x1 = __fsub_rn(cx, __fmul_rn(w, 0.5f));
                float y1 = __fsub_rn(cy, __fmul_rn(h, 0.5f));
                float x2 = __fadd_rn(cx, __fmul_rn(w, 0.5f));
                float y2 = __fadd_rn(cy, __fmul_rn(h, 0.5f));
                float clsf = (float)g_cls[b_my * NA + idx];
                float off  = __fmul_rn(clsf, MAXWH);
                float ox1 = __fadd_rn(x1, off), oy1 = __fadd_rn(y1, off);
                float ox2 = __fadd_rn(x2, off), oy2 = __fadd_rn(y2, off);

                int s = b_my * K_PRE + rank;
                g_bx  [s] = make_float4(ox1, oy1, ox2, oy2);
                g_area[s] = __fmul_rn(__fsub_rn(ox2, ox1), __fsub_rn(oy2, oy1));
                g_raw [s] = make_float4(x1, y1, x2, y2);
                g_sc  [s] = make_float2(score, clsf);
            }
        }
    }
    batch_bar(b_my);

    // ===== phase D+E: per-class IoU + Jacobi + output (block sub==0 only) =====
    if (sub != 0) return;
    {
        if (tid == 0) g_cnt[b_my] = 0;   // last reader was phase C

        float4* jb4 = (float4*)ubuf;                    // 1024 * 16B
        float*  ja  = (float*)(ubuf + 1024 * 16);       // 1024 * 4B

        jb4[tid] = g_bx  [b_my * K_PRE + tid];
        ja [tid] = g_area[b_my * K_PRE + tid];
        float2 sc = g_sc[b_my * K_PRE + tid];
        bool valid = sc.x > 0.0f;
        int  cls   = (int)sc.y;

        if (tid < NCLS) ccnt[tid] = 0;
        __syncthreads();
        int mypos = -1;
        if (valid) mypos = atomicAdd(&ccnt[cls], 1);
        __syncthreads();
        if (tid == 0) {
            int s = 0;
            for (int c = 0; c < NCLS; c++) { cbase[c] = s; s += ccnt[c]; }
            cbase[NCLS] = s;
        }
        __syncthreads();
        if (valid) clist[cbase[cls] + mypos] = (uint16_t)tid;
        __syncthreads();

        // same-class suppression only (cross-class IoU is exactly 0 by offset)
        if (valid) {
            float4 ib = jb4[tid];
            float  ia = ja [tid];
            int s0 = cbase[cls], s1 = cbase[cls + 1];
            for (int q = s0; q < s1; q++) {
                int r = clist[q];
                if (r >= tid) continue;                 // only lower rank suppresses
                float4 ob = jb4[r];
                float ltx = fmaxf(ib.x, ob.x), lty = fmaxf(ib.y, ob.y);
                float rbx = fminf(ib.z, ob.z), rby = fminf(ib.w, ob.w);
                float ww = fmaxf(__fsub_rn(rbx, ltx), 0.0f);
                float hh = fmaxf(__fsub_rn(rby, lty), 0.0f);
                float inter = __fmul_rn(ww, hh);
                float uni   = __fadd_rn(__fsub_rn(__fadd_rn(ia, ja[r]), inter), 1e-7f);
                float iou   = __fdiv_rn(inter, uni);
                if (iou > IOU_T)
                    atomicOr(&g_maskT[(b_my * 32 + (r >> 5)) * K_PRE + tid],
                             1u << (r & 31));
            }
        }
        __syncthreads();    // block-scope: atomics above visible to loads below

        // ---- Jacobi greedy-NMS + output ----
        int b = b_my, t = tid;

        uint32_t row[32];
        #pragma unroll
        for (int w = 0; w < 32; w++) row[w] = g_maskT[(b * 32 + w) * K_PRE + t];

        {
            unsigned bal = __ballot_sync(F, valid);
            if (lane == 0) keep_s[wid] = bal;
        }
        __syncthreads();

        for (int it = 0; it < K_PRE; it++) {
            uint32_t acc = 0;
            #pragma unroll
            for (int w = 0; w < 32; w++) acc |= row[w] & keep_s[w];
            int nb  = (valid && acc == 0) ? 1 : 0;
            int old = (keep_s[wid] >> lane) & 1;
            __syncthreads();
            unsigned nbal = __ballot_sync(F, nb);
            if (lane == 0) keep_s[wid] = nbal;
            int changed = __syncthreads_or(nb != old);
            if (!changed) break;
        }

        if (t == 0) {
            pfx[0] = 0;
            for (int w = 0; w < 32; w++) pfx[w + 1] = pfx[w] + __popc(keep_s[w]);
        }
        __syncthreads();

        uint32_t kw = keep_s[wid];
        if (valid && ((kw >> lane) & 1)) {
            int rank = pfx[wid] + __popc(kw & ((1u << lane) - 1u));
            if (rank < MAX_DET) {
                float4 r = g_raw[b * K_PRE + t];
                float* o = out + ((size_t)b * MAX_DET + rank) * 6;
                o[0] = r.x; o[1] = r.y; o[2] = r.z; o[3] = r.w;
                o[4] = sc.x; o[5] = sc.y;
            }
        }
    }
}

// ---------------- launcher ----------------
extern "C" void kernel_launch(void* const* d_in, const int* in_sizes, int n_in,
                              void* d_out, int out_size) {
    (void)in_sizes; (void)n_in; (void)out_size;
    const float* pred = (const float*)d_in[0];
    float* out = (float*)d_out;

    static int configured = 0;
    if (!configured) {
        cudaFuncSetAttribute(score_kernel,
                             cudaFuncAttributeMaxDynamicSharedMemorySize, 2 * TILE_B);
        configured = 1;
    }

    score_kernel<<<SGRID, S_ANCH, 2 * TILE_B>>>(pred);
    tail_kernel <<<TGRID, 1024>>>(pred, out);
}